// round 2
// baseline (speedup 1.0000x reference)
#include <cuda_runtime.h>

#define NN 50000
#define EE 800000
#define EP 850000   /* EE + NN self loops */
#define FDIM 64     /* HEADS*HID */
#define OUTC 40

// ---------------- device scratch (no allocation allowed) ----------------
__device__ int    g_is64;
__device__ int    g_src[EE];
__device__ int    g_dst[EE];
__device__ int    g_deg[NN];
__device__ int    g_off[NN];
__device__ int    g_cur[NN];
__device__ int    g_csr_src[EP];
__device__ int    g_bsums[64];
__device__ float  g_bufA[NN * FDIM];
__device__ float  g_bufB[NN * FDIM];
__device__ float4 g_as4[NN];
__device__ float4 g_ad4[NN];
__device__ float  g_stats0[2 * FDIM];
__device__ float  g_stats1[2 * FDIM];
__device__ float  g_scale0[FDIM], g_shift0[FDIM], g_scale1[FDIM], g_shift1[FDIM];

// ---------------- dtype detection: int64 edge_index has zero high words ----
__global__ void k_detect(const unsigned* __restrict__ w) {
    __shared__ int nz;
    if (threadIdx.x == 0) nz = 0;
    __syncthreads();
    if (w[2 * threadIdx.x + 1] != 0u) atomicAdd(&nz, 1);
    __syncthreads();
    if (threadIdx.x == 0) g_is64 = (nz == 0) ? 1 : 0;
}

__global__ void k_zero() {
    int i = blockIdx.x * blockDim.x + threadIdx.x;
    if (i < NN) { g_deg[i] = 1; g_cur[i] = 0; }   // deg starts at 1: self loop
    if (i < 2 * FDIM) { g_stats0[i] = 0.f; g_stats1[i] = 0.f; }
}

// convert dtype + count degrees in one pass
__global__ void k_convcnt(const void* __restrict__ ei) {
    int i = blockIdx.x * blockDim.x + threadIdx.x;
    if (i >= EE) return;
    int s, d;
    if (g_is64) {
        const long long* p = (const long long*)ei;
        s = (int)p[i]; d = (int)p[EE + i];
    } else {
        const int* p = (const int*)ei;
        s = p[i]; d = p[EE + i];
    }
    g_src[i] = s; g_dst[i] = d;
    atomicAdd(&g_deg[d], 1);
}

// ---------------- exclusive scan of g_deg -> g_off ----------------
__global__ void k_scan1() {
    __shared__ int sm[1024];
    int i = blockIdx.x * 1024 + threadIdx.x;
    int v = (i < NN) ? g_deg[i] : 0;
    sm[threadIdx.x] = v;
    __syncthreads();
    for (int d = 1; d < 1024; d <<= 1) {
        int t = (threadIdx.x >= d) ? sm[threadIdx.x - d] : 0;
        __syncthreads();
        sm[threadIdx.x] += t;
        __syncthreads();
    }
    if (i < NN) g_off[i] = sm[threadIdx.x] - v;
    if (threadIdx.x == 1023) g_bsums[blockIdx.x] = sm[1023];
}

// per-block prefix of bsums computed locally (merges old scan2+scan3)
__global__ void k_scan3() {
    __shared__ int base;
    if (threadIdx.x == 0) {
        int run = 0;
        for (int b = 0; b < blockIdx.x; b++) run += g_bsums[b];
        base = run;
    }
    __syncthreads();
    int i = blockIdx.x * 1024 + threadIdx.x;
    if (i < NN) g_off[i] += base;
}

__global__ void k_fill() {
    int i = blockIdx.x * blockDim.x + threadIdx.x;
    if (i >= EP) return;
    int d, s;
    if (i < EE) { d = g_dst[i]; s = g_src[i]; }
    else        { d = i - EE;   s = i - EE;   }
    int slot = g_off[d] + atomicAdd(&g_cur[d], 1);
    g_csr_src[slot] = s;
}

// ---------------- GEMM: Y[n,o] = sum_k BN(X[n,k]) * W[o,k] ----------------
template<int FIN, int FOUT>
__global__ void k_gemm(const float* __restrict__ X, const float* __restrict__ W,
                       const float* __restrict__ scale, const float* __restrict__ shift,
                       float* __restrict__ Y) {
    __shared__ float Ws[FIN * FOUT];   // [k*FOUT + o]
    __shared__ float xs[4][FIN];
    for (int i = threadIdx.x; i < FIN * FOUT; i += 256) {
        int o = i / FIN, k = i - o * FIN;
        Ws[k * FOUT + o] = W[i];
    }
    int rowBase = blockIdx.x * 64;
    for (int r0 = 0; r0 < 64; r0 += 4) {
        __syncthreads();
        for (int i = threadIdx.x; i < 4 * FIN; i += 256) {
            int r = i / FIN, k = i - r * FIN;
            int n = rowBase + r0 + r;
            float v = 0.f;
            if (n < NN) {
                v = X[n * FIN + k];
                if (scale) v = v * scale[k] + shift[k];
            }
            xs[r][k] = v;
        }
        __syncthreads();
        if (threadIdx.x < 4 * FOUT) {
            int o = threadIdx.x % FOUT, r = threadIdx.x / FOUT;
            int n = rowBase + r0 + r;
            if (n < NN) {
                float acc = 0.f;
                #pragma unroll 8
                for (int k = 0; k < FIN; k++) acc += xs[r][k] * Ws[k * FOUT + o];
                Y[n * FOUT + o] = acc;
            }
        }
    }
}

// ---------------- per-node attention coefficients ----------------
// H=4, C=16: each lane owns channels (2*lane, 2*lane+1); head = lane/8.
__global__ void k_alpha4(const float* __restrict__ Hl, const float* __restrict__ avs,
                         const float* __restrict__ avd) {
    int gw = (blockIdx.x * blockDim.x + threadIdx.x) >> 5;
    int lane = threadIdx.x & 31;
    if (gw >= NN) return;
    float2 v  = *(const float2*)&Hl[gw * 64 + 2 * lane];
    float2 ws = *(const float2*)&avs[2 * lane];
    float2 wd = *(const float2*)&avd[2 * lane];
    float ss = v.x * ws.x + v.y * ws.y;
    float sd = v.x * wd.x + v.y * wd.y;
    // reduce within 8-lane head groups
    #pragma unroll
    for (int s = 4; s; s >>= 1) {
        ss += __shfl_xor_sync(0xffffffffu, ss, s);
        sd += __shfl_xor_sync(0xffffffffu, sd, s);
    }
    float s1 = __shfl_sync(0xffffffffu, ss, 8);
    float s2 = __shfl_sync(0xffffffffu, ss, 16);
    float s3 = __shfl_sync(0xffffffffu, ss, 24);
    float d1 = __shfl_sync(0xffffffffu, sd, 8);
    float d2 = __shfl_sync(0xffffffffu, sd, 16);
    float d3 = __shfl_sync(0xffffffffu, sd, 24);
    if (lane == 0) {
        g_as4[gw] = make_float4(ss, s1, s2, s3);
        g_ad4[gw] = make_float4(sd, d1, d2, d3);
    }
}

// H=1, C=40
__global__ void k_alpha1(const float* __restrict__ Hl, const float* __restrict__ avs,
                         const float* __restrict__ avd) {
    int gw = (blockIdx.x * blockDim.x + threadIdx.x) >> 5;
    int lane = threadIdx.x & 31;
    if (gw >= NN) return;
    float a = Hl[gw * OUTC + lane];
    float ss = a * avs[lane];
    float sd = a * avd[lane];
    if (lane < 8) {
        float b = Hl[gw * OUTC + lane + 32];
        ss += b * avs[lane + 32];
        sd += b * avd[lane + 32];
    }
    #pragma unroll
    for (int s = 16; s; s >>= 1) {
        ss += __shfl_xor_sync(0xffffffffu, ss, s);
        sd += __shfl_xor_sync(0xffffffffu, sd, s);
    }
    if (lane == 0) {
        g_as4[gw] = make_float4(ss, 0.f, 0.f, 0.f);
        g_ad4[gw] = make_float4(sd, 0.f, 0.f, 0.f);
    }
}

__device__ __forceinline__ float lrelu(float x) { return x > 0.f ? x : 0.2f * x; }

// ---------------- warp-per-node softmax (no max pass) + aggregation --------
// H=4, C=16. Lane owns channels (2*lane, 2*lane+1); head = lane/8.
__global__ void k_agg4(const float* __restrict__ Hl, const float* __restrict__ bias,
                       float* __restrict__ Y) {
    int gw = (blockIdx.x * blockDim.x + threadIdx.x) >> 5;
    int lane = threadIdx.x & 31;
    if (gw >= NN) return;
    int off = g_off[gw], deg = g_deg[gw];
    float4 ad = g_ad4[gw];
    float accx = 0.f, accy = 0.f;

    if (deg <= 32) {
        // fast path: one edge per lane, e kept in registers — single CSR pass
        int s_l = 0;
        float e0 = 0.f, e1 = 0.f, e2 = 0.f, e3 = 0.f;
        if (lane < deg) {
            s_l = g_csr_src[off + lane];
            float4 as = g_as4[s_l];
            e0 = __expf(lrelu(as.x + ad.x));
            e1 = __expf(lrelu(as.y + ad.y));
            e2 = __expf(lrelu(as.z + ad.z));
            e3 = __expf(lrelu(as.w + ad.w));
        }
        float sm0 = e0, sm1 = e1, sm2 = e2, sm3 = e3;
        #pragma unroll
        for (int s = 16; s; s >>= 1) {
            sm0 += __shfl_xor_sync(0xffffffffu, sm0, s);
            sm1 += __shfl_xor_sync(0xffffffffu, sm1, s);
            sm2 += __shfl_xor_sync(0xffffffffu, sm2, s);
            sm3 += __shfl_xor_sync(0xffffffffu, sm3, s);
        }
        float an0 = e0 / (sm0 + 1e-16f);
        float an1 = e1 / (sm1 + 1e-16f);
        float an2 = e2 / (sm2 + 1e-16f);
        float an3 = e3 / (sm3 + 1e-16f);
        for (int j = 0; j < deg; j++) {
            int s = __shfl_sync(0xffffffffu, s_l, j);
            float a0 = __shfl_sync(0xffffffffu, an0, j);
            float a1 = __shfl_sync(0xffffffffu, an1, j);
            float a2 = __shfl_sync(0xffffffffu, an2, j);
            float a3 = __shfl_sync(0xffffffffu, an3, j);
            float a01 = (lane & 8) ? a1 : a0;
            float a23 = (lane & 8) ? a3 : a2;
            float c = (lane & 16) ? a23 : a01;
            float2 hv = *(const float2*)&Hl[s * 64 + 2 * lane];
            accx += hv.x * c;
            accy += hv.y * c;
        }
    } else {
        // general path: two passes
        float sm0 = 0.f, sm1 = 0.f, sm2 = 0.f, sm3 = 0.f;
        for (int i = lane; i < deg; i += 32) {
            int s = g_csr_src[off + i];
            float4 as = g_as4[s];
            sm0 += __expf(lrelu(as.x + ad.x));
            sm1 += __expf(lrelu(as.y + ad.y));
            sm2 += __expf(lrelu(as.z + ad.z));
            sm3 += __expf(lrelu(as.w + ad.w));
        }
        #pragma unroll
        for (int s = 16; s; s >>= 1) {
            sm0 += __shfl_xor_sync(0xffffffffu, sm0, s);
            sm1 += __shfl_xor_sync(0xffffffffu, sm1, s);
            sm2 += __shfl_xor_sync(0xffffffffu, sm2, s);
            sm3 += __shfl_xor_sync(0xffffffffu, sm3, s);
        }
        float r0 = 1.f / (sm0 + 1e-16f), r1 = 1.f / (sm1 + 1e-16f);
        float r2 = 1.f / (sm2 + 1e-16f), r3 = 1.f / (sm3 + 1e-16f);
        for (int i0 = 0; i0 < deg; i0 += 32) {
            int myi = i0 + lane;
            int s_l = 0;
            float an0 = 0.f, an1 = 0.f, an2 = 0.f, an3 = 0.f;
            if (myi < deg) {
                s_l = g_csr_src[off + myi];
                float4 as = g_as4[s_l];
                an0 = __expf(lrelu(as.x + ad.x)) * r0;
                an1 = __expf(lrelu(as.y + ad.y)) * r1;
                an2 = __expf(lrelu(as.z + ad.z)) * r2;
                an3 = __expf(lrelu(as.w + ad.w)) * r3;
            }
            int cnt = min(32, deg - i0);
            for (int j = 0; j < cnt; j++) {
                int s = __shfl_sync(0xffffffffu, s_l, j);
                float a0 = __shfl_sync(0xffffffffu, an0, j);
                float a1 = __shfl_sync(0xffffffffu, an1, j);
                float a2 = __shfl_sync(0xffffffffu, an2, j);
                float a3 = __shfl_sync(0xffffffffu, an3, j);
                float a01 = (lane & 8) ? a1 : a0;
                float a23 = (lane & 8) ? a3 : a2;
                float c = (lane & 16) ? a23 : a01;
                float2 hv = *(const float2*)&Hl[s * 64 + 2 * lane];
                accx += hv.x * c;
                accy += hv.y * c;
            }
        }
    }
    float2 b2 = *(const float2*)&bias[2 * lane];
    Y[gw * 64 + 2 * lane]     = accx + b2.x;
    Y[gw * 64 + 2 * lane + 1] = accy + b2.y;
}

// H=1, C=40
__global__ void k_agg1(const float* __restrict__ Hl, const float* __restrict__ bias,
                       float* __restrict__ Y) {
    int gw = (blockIdx.x * blockDim.x + threadIdx.x) >> 5;
    int lane = threadIdx.x & 31;
    if (gw >= NN) return;
    int off = g_off[gw], deg = g_deg[gw];
    float ad = g_ad4[gw].x;
    float acc0 = 0.f, acc1 = 0.f;

    if (deg <= 32) {
        int s_l = 0;
        float e = 0.f;
        if (lane < deg) {
            s_l = g_csr_src[off + lane];
            e = __expf(lrelu(g_as4[s_l].x + ad));
        }
        float sm = e;
        #pragma unroll
        for (int s = 16; s; s >>= 1) sm += __shfl_xor_sync(0xffffffffu, sm, s);
        float an = e / (sm + 1e-16f);
        for (int j = 0; j < deg; j++) {
            int s = __shfl_sync(0xffffffffu, s_l, j);
            float a = __shfl_sync(0xffffffffu, an, j);
            acc0 += Hl[s * OUTC + lane] * a;
            if (lane < 8) acc1 += Hl[s * OUTC + lane + 32] * a;
        }
    } else {
        float sm = 0.f;
        for (int i = lane; i < deg; i += 32)
            sm += __expf(lrelu(g_as4[g_csr_src[off + i]].x + ad));
        #pragma unroll
        for (int s = 16; s; s >>= 1) sm += __shfl_xor_sync(0xffffffffu, sm, s);
        float r = 1.f / (sm + 1e-16f);
        for (int i0 = 0; i0 < deg; i0 += 32) {
            int myi = i0 + lane;
            int s_l = 0; float an = 0.f;
            if (myi < deg) {
                s_l = g_csr_src[off + myi];
                an = __expf(lrelu(g_as4[s_l].x + ad)) * r;
            }
            int cnt = min(32, deg - i0);
            for (int j = 0; j < cnt; j++) {
                int s = __shfl_sync(0xffffffffu, s_l, j);
                float a = __shfl_sync(0xffffffffu, an, j);
                acc0 += Hl[s * OUTC + lane] * a;
                if (lane < 8) acc1 += Hl[s * OUTC + lane + 32] * a;
            }
        }
    }
    Y[gw * OUTC + lane] = acc0 + bias[lane];
    if (lane < 8) Y[gw * OUTC + lane + 32] = acc1 + bias[lane + 32];
}

// ---------------- batch norm ----------------
__global__ void k_bnstats(const float* __restrict__ Y, float* __restrict__ st) {
    int c4 = (threadIdx.x & 15) * 4;
    int rg = blockIdx.x * (blockDim.x >> 4) + (threadIdx.x >> 4);
    int stride = gridDim.x * (blockDim.x >> 4);
    float4 s = make_float4(0.f, 0.f, 0.f, 0.f);
    float4 q = make_float4(0.f, 0.f, 0.f, 0.f);
    for (int n = rg; n < NN; n += stride) {
        float4 v = *(const float4*)&Y[n * FDIM + c4];
        s.x += v.x; s.y += v.y; s.z += v.z; s.w += v.w;
        q.x += v.x * v.x; q.y += v.y * v.y; q.z += v.z * v.z; q.w += v.w * v.w;
    }
    atomicAdd(&st[c4 + 0], s.x); atomicAdd(&st[c4 + 1], s.y);
    atomicAdd(&st[c4 + 2], s.z); atomicAdd(&st[c4 + 3], s.w);
    atomicAdd(&st[FDIM + c4 + 0], q.x); atomicAdd(&st[FDIM + c4 + 1], q.y);
    atomicAdd(&st[FDIM + c4 + 2], q.z); atomicAdd(&st[FDIM + c4 + 3], q.w);
}

__global__ void k_bnfin(const float* __restrict__ st, const float* __restrict__ g,
                        const float* __restrict__ b, float* __restrict__ sc,
                        float* __restrict__ sh) {
    int c = threadIdx.x;
    if (c < FDIM) {
        float mean = st[c] * (1.f / NN);
        float var  = st[FDIM + c] * (1.f / NN) - mean * mean;
        float s = g[c] * rsqrtf(var + 1e-5f);
        sc[c] = s;
        sh[c] = b[c] - mean * s;
    }
}

// ---------------- log_softmax + output ----------------
__global__ void k_lsm(const float* __restrict__ emb, float* __restrict__ out, int writeEmb) {
    int gw = (blockIdx.x * blockDim.x + threadIdx.x) >> 5;
    int lane = threadIdx.x & 31;
    if (gw >= NN) return;
    float v0 = emb[gw * OUTC + lane];
    float v1 = (lane < 8) ? emb[gw * OUTC + lane + 32] : -1e30f;
    float m = fmaxf(v0, v1);
    for (int s = 16; s; s >>= 1) m = fmaxf(m, __shfl_xor_sync(0xffffffffu, m, s));
    float e = expf(v0 - m) + ((lane < 8) ? expf(v1 - m) : 0.f);
    for (int s = 16; s; s >>= 1) e += __shfl_xor_sync(0xffffffffu, e, s);
    float lse = m + logf(e);
    out[gw * OUTC + lane] = v0 - lse;
    if (lane < 8) out[gw * OUTC + lane + 32] = v1 - lse;
    if (writeEmb) {
        out[NN * OUTC + gw * OUTC + lane] = v0;
        if (lane < 8) out[NN * OUTC + gw * OUTC + lane + 32] = v1;
    }
}

// ---------------- launcher ----------------
extern "C" void kernel_launch(void* const* d_in, const int* in_sizes, int n_in,
                              void* d_out, int out_size) {
    const float* x   = (const float*)d_in[0];
    const void*  ei  = d_in[1];
    const float* W0  = (const float*)d_in[2];
    const float* as0 = (const float*)d_in[3];
    const float* ad0 = (const float*)d_in[4];
    const float* b0  = (const float*)d_in[5];
    const float* W1  = (const float*)d_in[6];
    const float* as1 = (const float*)d_in[7];
    const float* ad1 = (const float*)d_in[8];
    const float* b1  = (const float*)d_in[9];
    const float* W2  = (const float*)d_in[10];
    const float* as2 = (const float*)d_in[11];
    const float* ad2 = (const float*)d_in[12];
    const float* b2  = (const float*)d_in[13];
    const float* g0  = (const float*)d_in[14];
    const float* bt0 = (const float*)d_in[15];
    const float* g1  = (const float*)d_in[16];
    const float* bt1 = (const float*)d_in[17];
    float* out = (float*)d_out;

    float *bufA, *bufB, *st0, *st1, *sc0, *sh0, *sc1, *sh1;
    cudaGetSymbolAddress((void**)&bufA, g_bufA);
    cudaGetSymbolAddress((void**)&bufB, g_bufB);
    cudaGetSymbolAddress((void**)&st0, g_stats0);
    cudaGetSymbolAddress((void**)&st1, g_stats1);
    cudaGetSymbolAddress((void**)&sc0, g_scale0);
    cudaGetSymbolAddress((void**)&sh0, g_shift0);
    cudaGetSymbolAddress((void**)&sc1, g_scale1);
    cudaGetSymbolAddress((void**)&sh1, g_shift1);

    // ---- CSR build ----
    k_detect<<<1, 1024>>>((const unsigned*)ei);
    k_zero<<<(NN + 255) / 256, 256>>>();
    k_convcnt<<<(EE + 255) / 256, 256>>>(ei);
    k_scan1<<<49, 1024>>>();
    k_scan3<<<49, 1024>>>();
    k_fill<<<(EP + 255) / 256, 256>>>();

    const int GEMM_BLOCKS = (NN + 63) / 64;
    const int NODE_BLOCKS = (NN + 7) / 8;   // warp per node, 8 warps/block

    // ---- layer 0: 128 -> 4x16 ----
    k_gemm<128, 64><<<GEMM_BLOCKS, 256>>>(x, W0, nullptr, nullptr, bufA);
    k_alpha4<<<NODE_BLOCKS, 256>>>(bufA, as0, ad0);
    k_agg4<<<NODE_BLOCKS, 256>>>(bufA, b0, bufB);
    k_bnstats<<<128, 256>>>(bufB, st0);
    k_bnfin<<<1, 64>>>(st0, g0, bt0, sc0, sh0);

    // ---- layer 1: 64 -> 4x16 (BN fused into GEMM load) ----
    k_gemm<64, 64><<<GEMM_BLOCKS, 256>>>(bufB, W1, sc0, sh0, bufA);
    k_alpha4<<<NODE_BLOCKS, 256>>>(bufA, as1, ad1);
    k_agg4<<<NODE_BLOCKS, 256>>>(bufA, b1, bufB);
    k_bnstats<<<128, 256>>>(bufB, st1);
    k_bnfin<<<1, 64>>>(st1, g1, bt1, sc1, sh1);

    // ---- layer 2: 64 -> 40, 1 head, concat=False ----
    k_gemm<64, 40><<<GEMM_BLOCKS, 256>>>(bufB, W2, sc1, sh1, bufA);
    k_alpha1<<<NODE_BLOCKS, 256>>>(bufA, as2, ad2);
    k_agg1<<<NODE_BLOCKS, 256>>>(bufA, b2, bufB);

    int writeEmb = (out_size >= 2 * NN * OUTC) ? 1 : 0;
    k_lsm<<<NODE_BLOCKS, 256>>>(bufB, out, writeEmb);
}

// round 17
// speedup vs baseline: 1.6238x; 1.6238x over previous
#include <cuda_runtime.h>

#define NN 50000
#define EE 800000
#define EP 850000   /* EE + NN self loops */
#define FDIM 64     /* HEADS*HID */
#define OUTC 40

// ---------------- device scratch (no allocation allowed) ----------------
__device__ int    g_is64;
__device__ int    g_src[EE];
__device__ int    g_dst[EE];
__device__ int    g_deg[NN];
__device__ int    g_off[NN];
__device__ int    g_cur[NN];
__device__ int    g_csr_src[EP];
__device__ int    g_bsums[64];
__device__ float  g_bufA[NN * FDIM];
__device__ float  g_bufB[NN * FDIM];
__device__ float4 g_as4[NN];
__device__ float4 g_ad4[NN];
__device__ float  g_stats0[2 * FDIM];
__device__ float  g_stats1[2 * FDIM];
__device__ float  g_scale0[FDIM], g_shift0[FDIM], g_scale1[FDIM], g_shift1[FDIM];

// ---------------- dtype detection: int64 edge_index has zero high words ----
__global__ void k_detect(const unsigned* __restrict__ w) {
    __shared__ int nz;
    if (threadIdx.x == 0) nz = 0;
    __syncthreads();
    if (w[2 * threadIdx.x + 1] != 0u) atomicAdd(&nz, 1);
    __syncthreads();
    if (threadIdx.x == 0) g_is64 = (nz == 0) ? 1 : 0;
}

__global__ void k_zero() {
    int i = blockIdx.x * blockDim.x + threadIdx.x;
    if (i < NN) { g_deg[i] = 1; g_cur[i] = 0; }   // deg starts at 1: self loop
    if (i < 2 * FDIM) { g_stats0[i] = 0.f; g_stats1[i] = 0.f; }
}

// convert dtype + count degrees in one pass
__global__ void k_convcnt(const void* __restrict__ ei) {
    int i = blockIdx.x * blockDim.x + threadIdx.x;
    if (i >= EE) return;
    int s, d;
    if (g_is64) {
        const long long* p = (const long long*)ei;
        s = (int)p[i]; d = (int)p[EE + i];
    } else {
        const int* p = (const int*)ei;
        s = p[i]; d = p[EE + i];
    }
    g_src[i] = s; g_dst[i] = d;
    atomicAdd(&g_deg[d], 1);
}

// ---------------- exclusive scan of g_deg -> g_off (warp-shuffle based) ----
__global__ void k_scan1() {
    __shared__ int wsum[32];
    int lane = threadIdx.x & 31, warp = threadIdx.x >> 5;
    int i = blockIdx.x * 1024 + threadIdx.x;
    int v = (i < NN) ? g_deg[i] : 0;
    int x = v;
    #pragma unroll
    for (int s = 1; s < 32; s <<= 1) {
        int t = __shfl_up_sync(0xffffffffu, x, s);
        if (lane >= s) x += t;
    }
    if (lane == 31) wsum[warp] = x;
    __syncthreads();
    if (warp == 0) {
        int y = wsum[lane];
        #pragma unroll
        for (int s = 1; s < 32; s <<= 1) {
            int t = __shfl_up_sync(0xffffffffu, y, s);
            if (lane >= s) y += t;
        }
        wsum[lane] = y;
    }
    __syncthreads();
    int base = (warp > 0) ? wsum[warp - 1] : 0;
    if (i < NN) g_off[i] = base + x - v;   // exclusive
    if (threadIdx.x == 1023) g_bsums[blockIdx.x] = base + x;
}

__global__ void k_scan3() {
    __shared__ int base;
    if (threadIdx.x < 32) {
        int lane = threadIdx.x;
        int p = 0;
        if (lane < blockIdx.x) p += g_bsums[lane];
        if (lane + 32 < blockIdx.x) p += g_bsums[lane + 32];
        #pragma unroll
        for (int s = 16; s; s >>= 1) p += __shfl_xor_sync(0xffffffffu, p, s);
        if (lane == 0) base = p;
    }
    __syncthreads();
    int i = blockIdx.x * 1024 + threadIdx.x;
    if (i < NN) g_off[i] += base;
}

__global__ void k_fill() {
    int i = blockIdx.x * blockDim.x + threadIdx.x;
    if (i >= EP) return;
    int d, s;
    if (i < EE) { d = g_dst[i]; s = g_src[i]; }
    else        { d = i - EE;   s = i - EE;   }
    int slot = g_off[d] + atomicAdd(&g_cur[d], 1);
    g_csr_src[slot] = s;
}

// ---------------- register-tiled GEMM + fused alpha epilogue ----------------
// Y[n,o] = sum_k BN(X[n,k]) * W[o,k]; also writes g_as4/g_ad4 (per-head dots).
// Block: 64 rows x FOUT cols. Thread (ty,tx): rows 4ty..4ty+3, cols 4tx..4tx+3.
template<int FIN, int FOUT, int HEADS>
__global__ void k_gemm_alpha(const float* __restrict__ X, const float* __restrict__ W,
                             const float* __restrict__ scale, const float* __restrict__ shift,
                             const float* __restrict__ avs, const float* __restrict__ avd,
                             float* __restrict__ Y) {
    constexpr int NTX = FOUT / 4;      // 16 or 10
    constexpr int NTH = 16 * NTX;      // 256 or 160
    constexpr int XST = FIN + 1;
    constexpr int WST = FOUT + 4;
    constexpr int PST = NTX + 1;
    extern __shared__ float dsm[];
    float* xs = dsm;                       // [64][XST]
    float* ws = xs + 64 * XST;             // [FIN][WST]
    float* ps = ws + FIN * WST;            // [64][PST]
    float* pd = ps + 64 * PST;             // [64][PST]

    int tid = threadIdx.x;
    int tx = tid % NTX, ty = tid / NTX;
    int rowBase = blockIdx.x * 64;

    for (int i = tid; i < FIN * FOUT; i += NTH) {
        int o = i / FIN, k = i - o * FIN;
        ws[k * WST + o] = W[i];
    }
    for (int i = tid; i < 64 * FIN; i += NTH) {
        int r = i / FIN, k = i - r * FIN;
        int n = rowBase + r;
        float v = 0.f;
        if (n < NN) {
            v = X[n * FIN + k];
            if (scale) v = v * scale[k] + shift[k];
        }
        xs[r * XST + k] = v;
    }
    __syncthreads();

    float acc[4][4];
    #pragma unroll
    for (int i = 0; i < 4; i++)
        #pragma unroll
        for (int j = 0; j < 4; j++) acc[i][j] = 0.f;

    #pragma unroll 8
    for (int k = 0; k < FIN; k++) {
        float4 w4 = *(const float4*)&ws[k * WST + 4 * tx];
        float x0 = xs[(4 * ty + 0) * XST + k];
        float x1 = xs[(4 * ty + 1) * XST + k];
        float x2 = xs[(4 * ty + 2) * XST + k];
        float x3 = xs[(4 * ty + 3) * XST + k];
        acc[0][0] += x0 * w4.x; acc[0][1] += x0 * w4.y; acc[0][2] += x0 * w4.z; acc[0][3] += x0 * w4.w;
        acc[1][0] += x1 * w4.x; acc[1][1] += x1 * w4.y; acc[1][2] += x1 * w4.z; acc[1][3] += x1 * w4.w;
        acc[2][0] += x2 * w4.x; acc[2][1] += x2 * w4.y; acc[2][2] += x2 * w4.z; acc[2][3] += x2 * w4.w;
        acc[3][0] += x3 * w4.x; acc[3][1] += x3 * w4.y; acc[3][2] += x3 * w4.z; acc[3][3] += x3 * w4.w;
    }

    // write Y + alpha partials
    float4 aws = *(const float4*)&avs[4 * tx];
    float4 awd = *(const float4*)&avd[4 * tx];
    #pragma unroll
    for (int i = 0; i < 4; i++) {
        int n = rowBase + 4 * ty + i;
        float sa = acc[i][0] * aws.x + acc[i][1] * aws.y + acc[i][2] * aws.z + acc[i][3] * aws.w;
        float da = acc[i][0] * awd.x + acc[i][1] * awd.y + acc[i][2] * awd.z + acc[i][3] * awd.w;
        ps[(4 * ty + i) * PST + tx] = sa;
        pd[(4 * ty + i) * PST + tx] = da;
        if (n < NN) {
            float4 o4 = make_float4(acc[i][0], acc[i][1], acc[i][2], acc[i][3]);
            *(float4*)&Y[n * FOUT + 4 * tx] = o4;
        }
    }
    __syncthreads();

    if (HEADS == 4) {
        // 256 threads: row = tid>>2, head = tid&3; sum 4 tx slots of that head
        int row = tid >> 2, h = tid & 3;
        float s_ = 0.f, d_ = 0.f;
        #pragma unroll
        for (int t = 0; t < 4; t++) {
            s_ += ps[row * PST + 4 * h + t];
            d_ += pd[row * PST + 4 * h + t];
        }
        int n = rowBase + row;
        if (n < NN) {
            ((float*)&g_as4[n])[h] = s_;
            ((float*)&g_ad4[n])[h] = d_;
        }
    } else {
        if (tid < 64) {
            int row = tid;
            float s_ = 0.f, d_ = 0.f;
            #pragma unroll
            for (int t = 0; t < NTX; t++) {
                s_ += ps[row * PST + t];
                d_ += pd[row * PST + t];
            }
            int n = rowBase + row;
            if (n < NN) {
                g_as4[n] = make_float4(s_, 0.f, 0.f, 0.f);
                g_ad4[n] = make_float4(d_, 0.f, 0.f, 0.f);
            }
        }
    }
}

__device__ __forceinline__ float lrelu(float x) { return x > 0.f ? x : 0.2f * x; }

// ---------------- warp-per-node softmax + aggregation (H=4, C=16) ----------
// Lane owns channels (2*lane, 2*lane+1); head = lane>>3. smem-staged alphas.
__global__ void k_agg4(const float* __restrict__ Hl, const float* __restrict__ bias,
                       float* __restrict__ Y) {
    __shared__ float4 sa[8][32];
    __shared__ int    ss[8][32];
    int warp = threadIdx.x >> 5;
    int gw = (blockIdx.x * blockDim.x + threadIdx.x) >> 5;
    int lane = threadIdx.x & 31;
    if (gw >= NN) return;
    int off = g_off[gw], deg = g_deg[gw];
    float4 ad = g_ad4[gw];
    int h = lane >> 3;
    float accx = 0.f, accy = 0.f;

    if (deg <= 32) {
        int s_l = 0;
        float e0 = 0.f, e1 = 0.f, e2 = 0.f, e3 = 0.f;
        if (lane < deg) {
            s_l = g_csr_src[off + lane];
            float4 as = g_as4[s_l];
            e0 = __expf(lrelu(as.x + ad.x));
            e1 = __expf(lrelu(as.y + ad.y));
            e2 = __expf(lrelu(as.z + ad.z));
            e3 = __expf(lrelu(as.w + ad.w));
        }
        float sm0 = e0, sm1 = e1, sm2 = e2, sm3 = e3;
        #pragma unroll
        for (int s = 16; s; s >>= 1) {
            sm0 += __shfl_xor_sync(0xffffffffu, sm0, s);
            sm1 += __shfl_xor_sync(0xffffffffu, sm1, s);
            sm2 += __shfl_xor_sync(0xffffffffu, sm2, s);
            sm3 += __shfl_xor_sync(0xffffffffu, sm3, s);
        }
        sa[warp][lane] = make_float4(e0 / (sm0 + 1e-16f), e1 / (sm1 + 1e-16f),
                                     e2 / (sm2 + 1e-16f), e3 / (sm3 + 1e-16f));
        ss[warp][lane] = s_l;
        __syncwarp();
        for (int j = 0; j < deg; j++) {
            int s = ss[warp][j];
            float a = ((const float*)&sa[warp][j])[h];
            float2 hv = *(const float2*)&Hl[s * 64 + 2 * lane];
            accx += hv.x * a;
            accy += hv.y * a;
        }
    } else {
        float sm0 = 0.f, sm1 = 0.f, sm2 = 0.f, sm3 = 0.f;
        for (int i = lane; i < deg; i += 32) {
            int s = g_csr_src[off + i];
            float4 as = g_as4[s];
            sm0 += __expf(lrelu(as.x + ad.x));
            sm1 += __expf(lrelu(as.y + ad.y));
            sm2 += __expf(lrelu(as.z + ad.z));
            sm3 += __expf(lrelu(as.w + ad.w));
        }
        #pragma unroll
        for (int s = 16; s; s >>= 1) {
            sm0 += __shfl_xor_sync(0xffffffffu, sm0, s);
            sm1 += __shfl_xor_sync(0xffffffffu, sm1, s);
            sm2 += __shfl_xor_sync(0xffffffffu, sm2, s);
            sm3 += __shfl_xor_sync(0xffffffffu, sm3, s);
        }
        float r0 = 1.f / (sm0 + 1e-16f), r1 = 1.f / (sm1 + 1e-16f);
        float r2 = 1.f / (sm2 + 1e-16f), r3 = 1.f / (sm3 + 1e-16f);
        for (int i0 = 0; i0 < deg; i0 += 32) {
            int myi = i0 + lane;
            int s_l = 0;
            float4 an = make_float4(0.f, 0.f, 0.f, 0.f);
            if (myi < deg) {
                s_l = g_csr_src[off + myi];
                float4 as = g_as4[s_l];
                an.x = __expf(lrelu(as.x + ad.x)) * r0;
                an.y = __expf(lrelu(as.y + ad.y)) * r1;
                an.z = __expf(lrelu(as.z + ad.z)) * r2;
                an.w = __expf(lrelu(as.w + ad.w)) * r3;
            }
            __syncwarp();
            sa[warp][lane] = an;
            ss[warp][lane] = s_l;
            __syncwarp();
            int cnt = min(32, deg - i0);
            for (int j = 0; j < cnt; j++) {
                int s = ss[warp][j];
                float a = ((const float*)&sa[warp][j])[h];
                float2 hv = *(const float2*)&Hl[s * 64 + 2 * lane];
                accx += hv.x * a;
                accy += hv.y * a;
            }
        }
    }
    float2 b2 = *(const float2*)&bias[2 * lane];
    Y[gw * 64 + 2 * lane]     = accx + b2.x;
    Y[gw * 64 + 2 * lane + 1] = accy + b2.y;
}

// ---------------- layer-2 agg (H=1, C=40) + fused log_softmax --------------
__global__ void k_agg1lsm(const float* __restrict__ Hl, const float* __restrict__ bias,
                          float* __restrict__ out, int writeEmb) {
    __shared__ float sa[8][32];
    __shared__ int   ssb[8][32];
    int warp = threadIdx.x >> 5;
    int gw = (blockIdx.x * blockDim.x + threadIdx.x) >> 5;
    int lane = threadIdx.x & 31;
    if (gw >= NN) return;
    int off = g_off[gw], deg = g_deg[gw];
    float ad = g_ad4[gw].x;
    float acc0 = 0.f, acc1 = 0.f;

    if (deg <= 32) {
        int s_l = 0;
        float e = 0.f;
        if (lane < deg) {
            s_l = g_csr_src[off + lane];
            e = __expf(lrelu(g_as4[s_l].x + ad));
        }
        float sm = e;
        #pragma unroll
        for (int s = 16; s; s >>= 1) sm += __shfl_xor_sync(0xffffffffu, sm, s);
        sa[warp][lane] = e / (sm + 1e-16f);
        ssb[warp][lane] = s_l;
        __syncwarp();
        for (int j = 0; j < deg; j++) {
            int s = ssb[warp][j];
            float a = sa[warp][j];
            acc0 += Hl[s * OUTC + lane] * a;
            if (lane < 8) acc1 += Hl[s * OUTC + lane + 32] * a;
        }
    } else {
        float sm = 0.f;
        for (int i = lane; i < deg; i += 32)
            sm += __expf(lrelu(g_as4[g_csr_src[off + i]].x + ad));
        #pragma unroll
        for (int s = 16; s; s >>= 1) sm += __shfl_xor_sync(0xffffffffu, sm, s);
        float r = 1.f / (sm + 1e-16f);
        for (int i0 = 0; i0 < deg; i0 += 32) {
            int myi = i0 + lane;
            int s_l = 0; float an = 0.f;
            if (myi < deg) {
                s_l = g_csr_src[off + myi];
                an = __expf(lrelu(g_as4[s_l].x + ad)) * r;
            }
            __syncwarp();
            sa[warp][lane] = an;
            ssb[warp][lane] = s_l;
            __syncwarp();
            int cnt = min(32, deg - i0);
            for (int j = 0; j < cnt; j++) {
                int s = ssb[warp][j];
                float a = sa[warp][j];
                acc0 += Hl[s * OUTC + lane] * a;
                if (lane < 8) acc1 += Hl[s * OUTC + lane + 32] * a;
            }
        }
    }
    float v0 = acc0 + bias[lane];
    float v1 = (lane < 8) ? (acc1 + bias[lane + 32]) : -1e30f;
    float m = fmaxf(v0, v1);
    #pragma unroll
    for (int s = 16; s; s >>= 1) m = fmaxf(m, __shfl_xor_sync(0xffffffffu, m, s));
    float e = expf(v0 - m) + ((lane < 8) ? expf(v1 - m) : 0.f);
    #pragma unroll
    for (int s = 16; s; s >>= 1) e += __shfl_xor_sync(0xffffffffu, e, s);
    float lse = m + logf(e);
    out[gw * OUTC + lane] = v0 - lse;
    if (lane < 8) out[gw * OUTC + lane + 32] = v1 - lse;
    if (writeEmb) {
        out[NN * OUTC + gw * OUTC + lane] = v0;
        if (lane < 8) out[NN * OUTC + gw * OUTC + lane + 32] = v1;
    }
}

// ---------------- batch norm ----------------
__global__ void k_bnstats(const float* __restrict__ Y, float* __restrict__ st) {
    int c4 = (threadIdx.x & 15) * 4;
    int rg = blockIdx.x * (blockDim.x >> 4) + (threadIdx.x >> 4);
    int stride = gridDim.x * (blockDim.x >> 4);
    float4 s = make_float4(0.f, 0.f, 0.f, 0.f);
    float4 q = make_float4(0.f, 0.f, 0.f, 0.f);
    for (int n = rg; n < NN; n += stride) {
        float4 v = *(const float4*)&Y[n * FDIM + c4];
        s.x += v.x; s.y += v.y; s.z += v.z; s.w += v.w;
        q.x += v.x * v.x; q.y += v.y * v.y; q.z += v.z * v.z; q.w += v.w * v.w;
    }
    atomicAdd(&st[c4 + 0], s.x); atomicAdd(&st[c4 + 1], s.y);
    atomicAdd(&st[c4 + 2], s.z); atomicAdd(&st[c4 + 3], s.w);
    atomicAdd(&st[FDIM + c4 + 0], q.x); atomicAdd(&st[FDIM + c4 + 1], q.y);
    atomicAdd(&st[FDIM + c4 + 2], q.z); atomicAdd(&st[FDIM + c4 + 3], q.w);
}

__global__ void k_bnfin(const float* __restrict__ st, const float* __restrict__ g,
                        const float* __restrict__ b, float* __restrict__ sc,
                        float* __restrict__ sh) {
    int c = threadIdx.x;
    if (c < FDIM) {
        float mean = st[c] * (1.f / NN);
        float var  = st[FDIM + c] * (1.f / NN) - mean * mean;
        float s = g[c] * rsqrtf(var + 1e-5f);
        sc[c] = s;
        sh[c] = b[c] - mean * s;
    }
}

// ---------------- launcher ----------------
extern "C" void kernel_launch(void* const* d_in, const int* in_sizes, int n_in,
                              void* d_out, int out_size) {
    const float* x   = (const float*)d_in[0];
    const void*  ei  = d_in[1];
    const float* W0  = (const float*)d_in[2];
    const float* as0 = (const float*)d_in[3];
    const float* ad0 = (const float*)d_in[4];
    const float* b0  = (const float*)d_in[5];
    const float* W1  = (const float*)d_in[6];
    const float* as1 = (const float*)d_in[7];
    const float* ad1 = (const float*)d_in[8];
    const float* b1  = (const float*)d_in[9];
    const float* W2  = (const float*)d_in[10];
    const float* as2 = (const float*)d_in[11];
    const float* ad2 = (const float*)d_in[12];
    const float* b2  = (const float*)d_in[13];
    const float* g0  = (const float*)d_in[14];
    const float* bt0 = (const float*)d_in[15];
    const float* g1  = (const float*)d_in[16];
    const float* bt1 = (const float*)d_in[17];
    float* out = (float*)d_out;

    float *bufA, *bufB, *st0, *st1, *sc0, *sh0, *sc1, *sh1;
    cudaGetSymbolAddress((void**)&bufA, g_bufA);
    cudaGetSymbolAddress((void**)&bufB, g_bufB);
    cudaGetSymbolAddress((void**)&st0, g_stats0);
    cudaGetSymbolAddress((void**)&st1, g_stats1);
    cudaGetSymbolAddress((void**)&sc0, g_scale0);
    cudaGetSymbolAddress((void**)&sh0, g_shift0);
    cudaGetSymbolAddress((void**)&sc1, g_scale1);
    cudaGetSymbolAddress((void**)&sh1, g_shift1);

    // dynamic smem sizes: (xs + ws + ps + pd) * 4 bytes
    const int S0 = (64 * 129 + 128 * 68 + 2 * 64 * 17) * 4;  // 76544
    const int S1 = (64 * 65 + 64 * 68 + 2 * 64 * 17) * 4;    // 42752
    const int S2 = (64 * 65 + 64 * 44 + 2 * 64 * 11) * 4;    // 33536
    cudaFuncSetAttribute(k_gemm_alpha<128, 64, 4>, cudaFuncAttributeMaxDynamicSharedMemorySize, S0);
    cudaFuncSetAttribute(k_gemm_alpha<64, 64, 4>,  cudaFuncAttributeMaxDynamicSharedMemorySize, S1);
    cudaFuncSetAttribute(k_gemm_alpha<64, 40, 1>,  cudaFuncAttributeMaxDynamicSharedMemorySize, S2);

    // ---- CSR build ----
    k_detect<<<1, 1024>>>((const unsigned*)ei);
    k_zero<<<(NN + 255) / 256, 256>>>();
    k_convcnt<<<(EE + 255) / 256, 256>>>(ei);
    k_scan1<<<49, 1024>>>();
    k_scan3<<<49, 1024>>>();
    k_fill<<<(EP + 255) / 256, 256>>>();

    const int GB = (NN + 63) / 64;          // 782 gemm blocks
    const int NB = (NN + 7) / 8;            // warp per node, 8 warps/block

    // ---- layer 0: 128 -> 4x16 ----
    k_gemm_alpha<128, 64, 4><<<GB, 256, S0>>>(x, W0, nullptr, nullptr, as0, ad0, bufA);
    k_agg4<<<NB, 256>>>(bufA, b0, bufB);
    k_bnstats<<<128, 256>>>(bufB, st0);
    k_bnfin<<<1, 64>>>(st0, g0, bt0, sc0, sh0);

    // ---- layer 1: 64 -> 4x16 (BN fused into GEMM load) ----
    k_gemm_alpha<64, 64, 4><<<GB, 256, S1>>>(bufB, W1, sc0, sh0, as1, ad1, bufA);
    k_agg4<<<NB, 256>>>(bufA, b1, bufB);
    k_bnstats<<<128, 256>>>(bufB, st1);
    k_bnfin<<<1, 64>>>(st1, g1, bt1, sc1, sh1);

    // ---- layer 2: 64 -> 40, 1 head, concat=False; log_softmax fused ----
    k_gemm_alpha<64, 40, 1><<<GB, 160, S2>>>(bufB, W2, sc1, sh1, as2, ad2, bufA);
    int writeEmb = (out_size >= 2 * NN * OUTC) ? 1 : 0;
    k_agg1lsm<<<NB, 256>>>(bufA, b2, out, writeEmb);
}